// round 1
// baseline (speedup 1.0000x reference)
#include <cuda_runtime.h>

#define B_   8
#define L_   4096
#define C_   1024
#define D_   1024
#define NS   256
#define MLPD 512
#define TIT  6
#define LNEPS 1e-5f

typedef unsigned long long u64;

// ---------------- scratch (device globals; no allocations allowed) ----------
__device__ float g_xn[B_ * L_ * C_];          // 128 MB  normalized input [B*L, C]
__device__ float g_k [B_ * L_ * D_];          // 128 MB  [B, L, D]
__device__ float g_v [B_ * L_ * D_];          // 128 MB  [B, L, D]
__device__ float g_t  [B_ * NS * D_];         // templates [B*N, D]
__device__ float g_tln[B_ * NS * D_];         // LN(templates)
__device__ float g_q  [B_ * NS * D_];         // q
__device__ float g_attn[B_ * L_ * NS];        // 33.5 MB logits/attn [B, L, N]
__device__ float g_colpart[32 * B_ * NS];     // partial column sums
__device__ float g_colsum[B_ * NS];           // column sums
__device__ float g_hid[B_ * NS * MLPD];       // MLP hidden

// ---------------- f32x2 helpers ---------------------------------------------
__device__ __forceinline__ u64 pack2(float x) {
    u64 r; asm("mov.b64 %0, {%1, %1};" : "=l"(r) : "f"(x)); return r;
}
__device__ __forceinline__ void ffma2(u64 &d, u64 a, u64 b) {
    asm("fma.rn.f32x2 %0, %1, %2, %0;" : "+l"(d) : "l"(a), "l"(b));
}
__device__ __forceinline__ float2 unpack2(u64 v) {
    float2 f; asm("mov.b64 {%0, %1}, %2;" : "=f"(f.x), "=f"(f.y) : "l"(v)); return f;
}

// ---------------- broadcast templates_init ----------------------------------
__global__ void bcast_templates_kernel(const float* __restrict__ tinit,
                                       float* __restrict__ t) {
    int idx = blockIdx.x * blockDim.x + threadIdx.x;   // 8192*256 = 2,097,152
    t[idx] = tinit[idx & (NS * D_ - 1)];
}

// ---------------- LN over channels + transpose: x[B,C,L] -> xn[B,L,C] -------
__global__ void ln_transpose_kernel(const float* __restrict__ x,
                                    const float* __restrict__ g,
                                    const float* __restrict__ bt,
                                    float* __restrict__ xn) {
    int b  = blockIdx.y;
    int l0 = blockIdx.x * 32;
    int tx = threadIdx.x, ty = threadIdx.y;           // 32 x 8
    __shared__ float ssum[8][32];
    __shared__ float ssq [8][32];
    __shared__ float smean[32], srstd[32];
    const float* xb = x + (long)b * C_ * L_;
    float s = 0.f, q = 0.f;
    for (int c = ty; c < C_; c += 8) {
        float v = xb[(long)c * L_ + l0 + tx];
        s += v; q += v * v;
    }
    ssum[ty][tx] = s; ssq[ty][tx] = q;
    __syncthreads();
    if (ty == 0) {
        float ts = 0.f, tq = 0.f;
        #pragma unroll
        for (int i = 0; i < 8; i++) { ts += ssum[i][tx]; tq += ssq[i][tx]; }
        float mean = ts * (1.0f / C_);
        float var  = tq * (1.0f / C_) - mean * mean;
        smean[tx] = mean;
        srstd[tx] = rsqrtf(var + LNEPS);
    }
    __syncthreads();
    __shared__ float tile[32][33];
    float* outb = xn + ((long)b * L_ + l0) * C_;
    for (int c0 = 0; c0 < C_; c0 += 32) {
        __syncthreads();
        for (int cc = ty; cc < 32; cc += 8) {
            float v = xb[(long)(c0 + cc) * L_ + l0 + tx];
            tile[cc][tx] = (v - smean[tx]) * srstd[tx];
        }
        __syncthreads();
        for (int ll = ty; ll < 32; ll += 8) {
            int c = c0 + tx;
            outb[(long)ll * C_ + c] = tile[tx][ll] * g[c] + bt[c];
        }
    }
}

// ---------------- LN over rows of [rows, 1024] -------------------------------
__global__ void ln_rows_kernel(const float* __restrict__ in,
                               const float* __restrict__ g,
                               const float* __restrict__ bt,
                               float* __restrict__ out) {
    int row = blockIdx.x;
    int tid = threadIdx.x;                             // 256
    const float4* pin = (const float4*)(in + (long)row * D_);
    float4 v = pin[tid];
    float s = v.x + v.y + v.z + v.w;
    float q = v.x*v.x + v.y*v.y + v.z*v.z + v.w*v.w;
    #pragma unroll
    for (int o = 16; o > 0; o >>= 1) {
        s += __shfl_down_sync(0xffffffffu, s, o);
        q += __shfl_down_sync(0xffffffffu, q, o);
    }
    __shared__ float ws[8], wq[8];
    __shared__ float sm, sr;
    int warp = tid >> 5, lane = tid & 31;
    if (lane == 0) { ws[warp] = s; wq[warp] = q; }
    __syncthreads();
    if (tid == 0) {
        float ts = 0.f, tq = 0.f;
        #pragma unroll
        for (int i = 0; i < 8; i++) { ts += ws[i]; tq += wq[i]; }
        float mean = ts * (1.0f / D_);
        float var  = tq * (1.0f / D_) - mean * mean;
        sm = mean; sr = rsqrtf(var + LNEPS);
    }
    __syncthreads();
    float mean = sm, rstd = sr;
    float4 gg = ((const float4*)g)[tid];
    float4 bb = ((const float4*)bt)[tid];
    float4 o;
    o.x = (v.x - mean) * rstd * gg.x + bb.x;
    o.y = (v.y - mean) * rstd * gg.y + bb.y;
    o.z = (v.z - mean) * rstd * gg.z + bb.z;
    o.w = (v.w - mean) * rstd * gg.w + bb.w;
    ((float4*)(out + (long)row * D_))[tid] = o;
}

// ---------------- softmax over N (row of 256), one warp per row --------------
__global__ void softmax_kernel(float* __restrict__ attn) {
    int warp = threadIdx.x >> 5, lane = threadIdx.x & 31;
    long row = (long)blockIdx.x * 8 + warp;
    float* p = attn + row * NS;
    float4 a = ((float4*)p)[lane];
    float4 c = ((float4*)p)[lane + 32];
    float m = fmaxf(fmaxf(fmaxf(a.x, a.y), fmaxf(a.z, a.w)),
                    fmaxf(fmaxf(c.x, c.y), fmaxf(c.z, c.w)));
    #pragma unroll
    for (int o = 16; o > 0; o >>= 1) m = fmaxf(m, __shfl_xor_sync(0xffffffffu, m, o));
    a.x = __expf(a.x - m); a.y = __expf(a.y - m);
    a.z = __expf(a.z - m); a.w = __expf(a.w - m);
    c.x = __expf(c.x - m); c.y = __expf(c.y - m);
    c.z = __expf(c.z - m); c.w = __expf(c.w - m);
    float s = (a.x + a.y + a.z + a.w) + (c.x + c.y + c.z + c.w);
    #pragma unroll
    for (int o = 16; o > 0; o >>= 1) s += __shfl_xor_sync(0xffffffffu, s, o);
    float inv = 1.0f / s;
    a.x = a.x * inv + 1e-8f; a.y = a.y * inv + 1e-8f;
    a.z = a.z * inv + 1e-8f; a.w = a.w * inv + 1e-8f;
    c.x = c.x * inv + 1e-8f; c.y = c.y * inv + 1e-8f;
    c.z = c.z * inv + 1e-8f; c.w = c.w * inv + 1e-8f;
    ((float4*)p)[lane]      = a;
    ((float4*)p)[lane + 32] = c;
}

// ---------------- deterministic column sums over L ---------------------------
__global__ void colpart_kernel(const float* __restrict__ attn,
                               float* __restrict__ part) {
    int b  = blockIdx.y;
    int ch = blockIdx.x;                    // 32 chunks of 128 l's
    int n  = threadIdx.x;                   // 256
    const float* p = attn + ((long)b * L_ + ch * 128) * NS + n;
    float s0 = 0.f, s1 = 0.f, s2 = 0.f, s3 = 0.f;
    #pragma unroll 4
    for (int i = 0; i < 128; i += 4) {
        s0 += p[(long)(i+0) * NS]; s1 += p[(long)(i+1) * NS];
        s2 += p[(long)(i+2) * NS]; s3 += p[(long)(i+3) * NS];
    }
    part[(long)ch * B_ * NS + b * NS + n] = (s0 + s1) + (s2 + s3);
}
__global__ void colreduce_kernel(const float* __restrict__ part,
                                 float* __restrict__ colsum) {
    int idx = blockIdx.x * blockDim.x + threadIdx.x;  // B_*NS = 2048
    float s = 0.f;
    #pragma unroll
    for (int c = 0; c < 32; c++) s += part[(long)c * B_ * NS + idx];
    colsum[idx] = s;
}

// ---------------- tiled GEMM with f32x2 FMA ---------------------------------
// TA=0: A is [M,K] row-major; TA=1: A is [K,M] row-major (TN gemm).
// TB=0: B is [K,N] row-major; TB=1: B is [N,K] row-major (NT gemm).
#define BM 128
#define BN 128
#define BK 16
enum { EPI_NONE = 0, EPI_SCALE = 1, EPI_BIAS_RELU = 2, EPI_ADD_BIAS = 3, EPI_UPDATE = 4 };

template<int TA, int TB, int EPI>
__global__ void gemm_kernel(const float* __restrict__ Ag, const float* __restrict__ Bg,
                            float* __restrict__ Cg, const float* __restrict__ Crg,
                            const float* __restrict__ biasg, const float* __restrict__ rsg,
                            float alpha, int M, int N, int K,
                            long batA, long batB, long batC, int batS) {
    const float* A  = Ag  + (long)blockIdx.z * batA;
    const float* Bp = Bg  + (long)blockIdx.z * batB;
    float*       C  = Cg  + (long)blockIdx.z * batC;
    const float* Cr = Crg + (long)blockIdx.z * batC;
    const float* RS = rsg + (long)blockIdx.z * batS;

    __shared__ float As[BK][BM + 4];
    __shared__ float Bs[BK][BN + 4];

    const int tid = threadIdx.x;
    const int m0 = blockIdx.y * BM;
    const int n0 = blockIdx.x * BN;
    const int tx = tid & 15, ty = tid >> 4;
    const int tm = ty * 8, tn = tx * 8;

    u64 acc[8][4];
    #pragma unroll
    for (int i = 0; i < 8; i++)
        #pragma unroll
        for (int j = 0; j < 4; j++) acc[i][j] = 0ULL;

    const int ktiles = K / BK;

    auto load_g = [&](int kt, float4 ra[2], float4 rb[2]) {
        int k0 = kt * BK;
        #pragma unroll
        for (int it = 0; it < 2; it++) {
            int f = tid + it * 256;
            if (TA == 0) {
                int m = f >> 2, kq = f & 3;
                ra[it] = *(const float4*)(A + (long)(m0 + m) * K + k0 + kq * 4);
            } else {
                int kk = f >> 5, mq = f & 31;
                ra[it] = *(const float4*)(A + (long)(k0 + kk) * M + m0 + mq * 4);
            }
            if (TB == 0) {
                int kk = f >> 5, nq = f & 31;
                rb[it] = *(const float4*)(Bp + (long)(k0 + kk) * N + n0 + nq * 4);
            } else {
                int n = f >> 2, kq = f & 3;
                rb[it] = *(const float4*)(Bp + (long)(n0 + n) * K + k0 + kq * 4);
            }
        }
    };
    auto store_s = [&](float4 ra[2], float4 rb[2]) {
        #pragma unroll
        for (int it = 0; it < 2; it++) {
            int f = tid + it * 256;
            if (TA == 0) {
                int m = f >> 2, kq = f & 3;
                As[kq*4+0][m] = ra[it].x; As[kq*4+1][m] = ra[it].y;
                As[kq*4+2][m] = ra[it].z; As[kq*4+3][m] = ra[it].w;
            } else {
                int kk = f >> 5, mq = f & 31;
                *(float4*)&As[kk][mq*4] = ra[it];
            }
            if (TB == 0) {
                int kk = f >> 5, nq = f & 31;
                *(float4*)&Bs[kk][nq*4] = rb[it];
            } else {
                int n = f >> 2, kq = f & 3;
                Bs[kq*4+0][n] = rb[it].x; Bs[kq*4+1][n] = rb[it].y;
                Bs[kq*4+2][n] = rb[it].z; Bs[kq*4+3][n] = rb[it].w;
            }
        }
    };

    float4 ra[2], rb[2];
    load_g(0, ra, rb);
    store_s(ra, rb);
    __syncthreads();

    for (int t = 0; t < ktiles; t++) {
        float4 ra2[2], rb2[2];
        if (t + 1 < ktiles) load_g(t + 1, ra2, rb2);
        #pragma unroll
        for (int kk = 0; kk < BK; kk++) {
            float4 a0 = *(const float4*)&As[kk][tm];
            float4 a1 = *(const float4*)&As[kk][tm + 4];
            const u64* bp = (const u64*)&Bs[kk][tn];
            u64 b0 = bp[0], b1 = bp[1], b2 = bp[2], b3 = bp[3];
            u64 ap[8] = { pack2(a0.x), pack2(a0.y), pack2(a0.z), pack2(a0.w),
                          pack2(a1.x), pack2(a1.y), pack2(a1.z), pack2(a1.w) };
            #pragma unroll
            for (int i = 0; i < 8; i++) {
                ffma2(acc[i][0], ap[i], b0);
                ffma2(acc[i][1], ap[i], b1);
                ffma2(acc[i][2], ap[i], b2);
                ffma2(acc[i][3], ap[i], b3);
            }
        }
        if (t + 1 < ktiles) {
            __syncthreads();
            store_s(ra2, rb2);
            __syncthreads();
        }
    }

    #pragma unroll
    for (int i = 0; i < 8; i++) {
        int row = m0 + tm + i;
        float vals[8];
        #pragma unroll
        for (int j = 0; j < 4; j++) {
            float2 f = unpack2(acc[i][j]);
            vals[2*j] = f.x; vals[2*j+1] = f.y;
        }
        float rs = 0.f;
        if (EPI == EPI_UPDATE) rs = 1.0f / RS[row];
        float*       cp  = C  + (long)row * N + n0 + tn;
        const float* crp = Cr + (long)row * N + n0 + tn;
        #pragma unroll
        for (int j = 0; j < 8; j++) {
            int c = n0 + tn + j;
            float v = vals[j];
            if (EPI == EPI_SCALE)          v = v * alpha;
            else if (EPI == EPI_BIAS_RELU) v = fmaxf(v + biasg[c], 0.f);
            else if (EPI == EPI_ADD_BIAS)  v = crp[j] + v + biasg[c];
            else if (EPI == EPI_UPDATE)    v = crp[j] + v * rs;
            vals[j] = v;
        }
        *(float4*)cp       = make_float4(vals[0], vals[1], vals[2], vals[3]);
        *(float4*)(cp + 4) = make_float4(vals[4], vals[5], vals[6], vals[7]);
    }
}

// ---------------- outputs ----------------------------------------------------
__global__ void out_templates_kernel(const float* __restrict__ t, float* __restrict__ out) {
    int b  = blockIdx.z;
    int d0 = blockIdx.x * 32, n0 = blockIdx.y * 32;
    __shared__ float tile[32][33];
    int tx = threadIdx.x, ty = threadIdx.y;
    const float* tb = t + ((long)b * NS + n0) * D_ + d0;
    for (int nn = ty; nn < 32; nn += 8)
        tile[nn][tx] = tb[(long)nn * D_ + tx];
    __syncthreads();
    float* ob = out + ((long)b * D_ + d0) * NS + n0;
    for (int dd = ty; dd < 32; dd += 8)
        ob[(long)dd * NS + tx] = tile[tx][dd];
}

__global__ void out_attn_kernel(const float* __restrict__ attn,
                                const float* __restrict__ colsum,
                                float* __restrict__ out) {
    int b  = blockIdx.z;
    int l0 = blockIdx.x * 32, n0 = blockIdx.y * 32;
    __shared__ float tile[32][33];
    __shared__ float sinv[32];
    int tx = threadIdx.x, ty = threadIdx.y;
    if (ty == 0) sinv[tx] = 1.0f / colsum[b * NS + n0 + tx];
    __syncthreads();
    const float* ab = attn + ((long)b * L_ + l0) * NS + n0;
    for (int ll = ty; ll < 32; ll += 8)
        tile[ll][tx] = ab[(long)ll * NS + tx] * sinv[tx];
    __syncthreads();
    float* ob = out + ((long)b * NS + n0) * L_ + l0;
    for (int nn = ty; nn < 32; nn += 8)
        ob[(long)nn * L_ + tx] = tile[tx][nn];
}

// ---------------- driver -----------------------------------------------------
extern "C" void kernel_launch(void* const* d_in, const int* in_sizes, int n_in,
                              void* d_out, int out_size) {
    const float* x       = (const float*)d_in[0];
    const float* tinit   = (const float*)d_in[1];
    const float* Wq      = (const float*)d_in[2];
    const float* Wk      = (const float*)d_in[3];
    const float* Wv      = (const float*)d_in[4];
    const float* ln_in_g = (const float*)d_in[5];
    const float* ln_in_b = (const float*)d_in[6];
    const float* ln_t_g  = (const float*)d_in[7];
    const float* ln_t_b  = (const float*)d_in[8];
    const float* ln_m_g  = (const float*)d_in[9];
    const float* ln_m_b  = (const float*)d_in[10];
    const float* W1      = (const float*)d_in[11];
    const float* b1      = (const float*)d_in[12];
    const float* W2      = (const float*)d_in[13];
    const float* b2      = (const float*)d_in[14];
    float* out = (float*)d_out;

    float *xn, *k, *v, *t, *tln, *q, *attn, *colpart, *colsum, *hid;
    cudaGetSymbolAddress((void**)&xn,      g_xn);
    cudaGetSymbolAddress((void**)&k,       g_k);
    cudaGetSymbolAddress((void**)&v,       g_v);
    cudaGetSymbolAddress((void**)&t,       g_t);
    cudaGetSymbolAddress((void**)&tln,     g_tln);
    cudaGetSymbolAddress((void**)&q,       g_q);
    cudaGetSymbolAddress((void**)&attn,    g_attn);
    cudaGetSymbolAddress((void**)&colpart, g_colpart);
    cudaGetSymbolAddress((void**)&colsum,  g_colsum);
    cudaGetSymbolAddress((void**)&hid,     g_hid);

    const float scale = 0.03125f;  // 1024^-0.5

    bcast_templates_kernel<<<8192, 256>>>(tinit, t);
    ln_transpose_kernel<<<dim3(L_ / 32, B_), dim3(32, 8)>>>(x, ln_in_g, ln_in_b, xn);

    // k = xn @ Wk ; v = xn @ Wv   (flattened [B*L, C] @ [C, D])
    gemm_kernel<0,0,EPI_NONE><<<dim3(D_/BN, (B_*L_)/BM, 1), 256>>>(
        xn, Wk, k, k, b1, colsum, 1.f, B_*L_, D_, C_, 0, 0, 0, 0);
    gemm_kernel<0,0,EPI_NONE><<<dim3(D_/BN, (B_*L_)/BM, 1), 256>>>(
        xn, Wv, v, v, b1, colsum, 1.f, B_*L_, D_, C_, 0, 0, 0, 0);

    for (int it = 0; it < TIT; it++) {
        // t_ln = LN(t); q = t_ln @ Wq * scale
        ln_rows_kernel<<<B_*NS, 256>>>(t, ln_t_g, ln_t_b, tln);
        gemm_kernel<0,0,EPI_SCALE><<<dim3(D_/BN, (B_*NS)/BM, 1), 256>>>(
            tln, Wq, q, q, b1, colsum, scale, B_*NS, D_, D_, 0, 0, 0, 0);
        // logits[b,l,n] = k[b,l,:] . q[b,n,:]   (batched NT)
        gemm_kernel<0,1,EPI_NONE><<<dim3(NS/BN, L_/BM, B_), 256>>>(
            k, q, attn, attn, b1, colsum, 1.f, L_, NS, D_,
            (long)L_*D_, (long)NS*D_, (long)L_*NS, 0);
        // softmax over N + eps, then deterministic column sums over L
        softmax_kernel<<<(B_*L_)/8, 256>>>(attn);
        colpart_kernel<<<dim3(32, B_), 256>>>(attn, colpart);
        colreduce_kernel<<<8, 256>>>(colpart, colsum);
        // t += (attn/colsum)^T @ v   (batched TN with renorm epilogue)
        gemm_kernel<1,0,EPI_UPDATE><<<dim3(D_/BN, NS/BM, B_), 256>>>(
            attn, v, t, t, b1, colsum, 1.f, NS, D_, L_,
            (long)L_*NS, (long)L_*D_, (long)NS*D_, NS);
        // MLP residual
        ln_rows_kernel<<<B_*NS, 256>>>(t, ln_m_g, ln_m_b, tln);
        gemm_kernel<0,0,EPI_BIAS_RELU><<<dim3(MLPD/BN, (B_*NS)/BM, 1), 256>>>(
            tln, W1, hid, hid, b1, colsum, 1.f, B_*NS, MLPD, D_, 0, 0, 0, 0);
        gemm_kernel<0,0,EPI_ADD_BIAS><<<dim3(D_/BN, (B_*NS)/BM, 1), 256>>>(
            hid, W2, t, t, b2, colsum, 1.f, B_*NS, D_, MLPD, 0, 0, 0, 0);
    }

    out_templates_kernel<<<dim3(D_/32, NS/32, B_), dim3(32, 8)>>>(t, out);
    out_attn_kernel<<<dim3(L_/32, NS/32, B_), dim3(32, 8)>>>(
        attn, colsum, out + (long)B_ * D_ * NS);
}